// round 5
// baseline (speedup 1.0000x reference)
#include <cuda_runtime.h>
#include <cstdint>

// Decoder_2430951489916 — single kernel, counter-finalized accumulation.
//   B=4, N=512, M=512, ZD=128, YD=2, XD=1
// out[b,m,y] = b_y + sum_n sum_c W[y,c]*z[b,n,c]*exp(-0.5*((x_m-t_n)*exp(-sigma_c))^2)
// Fast path (uniform sigma, true for bench):
//   out[b,m,y] = b_y + sum_n exp(coef*(x_m-t_n)^2) * zw[b,n,y],  zw = z @ W^T.
//
// Structure: 256 blocks = 4 batches x 64 n-chunks (8 rows each), 512 threads.
// Each block reads its 8 z-rows exactly once (coalesced). Warps 0-7 build the
// zw chunk; meanwhile EVERY thread speculatively computes its 8 exp terms from
// t (staged first) so MUFU work overlaps the z-load + reduce chain.
// Partials go to zero-init __device__ scratch via relaxed red.add; a per-(b,m)
// acq_rel counter makes the 64th arriver finalize out = bias + acc and reset
// the scratch (graph-replay safe). No out pre-init, no flag spin, no fences.

#define BB 4
#define NN 512
#define MM 512
#define ZDIM 128
#define YDIM 2
#define CHUNK 8
#define NCHUNKS (NN / CHUNK)        // 64
#define NTHREADS 512
#define GRID (BB * NCHUNKS)         // 256
#define NCONTRIB NCHUNKS            // adds per output point

__device__ float    g_acc[BB * MM * YDIM];   // zero-init (.bss), self-resetting
__device__ unsigned g_cnt[BB * MM];          // zero-init (.bss), self-resetting

__device__ __forceinline__ void red_add_f32(float* p, float v) {
    asm volatile("red.relaxed.gpu.global.add.f32 [%0], %1;" :: "l"(p), "f"(v) : "memory");
}
__device__ __forceinline__ unsigned atom_inc_acqrel(unsigned* p) {
    unsigned old;
    asm volatile("atom.acq_rel.gpu.global.add.u32 %0, [%1], 1;" : "=r"(old) : "l"(p) : "memory");
    return old;
}
__device__ __forceinline__ float ld_relaxed_f32(const float* p) {
    float v;
    asm volatile("ld.relaxed.gpu.global.f32 %0, [%1];" : "=f"(v) : "l"(p) : "memory");
    return v;
}
__device__ __forceinline__ void st_relaxed_f32(float* p, float v) {
    asm volatile("st.relaxed.gpu.global.f32 [%0], %1;" :: "l"(p), "f"(v) : "memory");
}
__device__ __forceinline__ void st_relaxed_u32(unsigned* p, unsigned v) {
    asm volatile("st.relaxed.gpu.global.u32 [%0], %1;" :: "l"(p), "r"(v) : "memory");
}

__global__ __launch_bounds__(NTHREADS) void decoder_v5(
    const float* __restrict__ t,
    const float* __restrict__ z,
    const float* __restrict__ x,
    const float* __restrict__ sigma,
    const float* __restrict__ W,
    const float* __restrict__ bias,
    float* __restrict__ out) {
    __shared__ float t_s[CHUNK];
    __shared__ float zw0_s[CHUNK];
    __shared__ float zw1_s[CHUNK];
    __shared__ int   nonuniform;

    const int tid   = threadIdx.x;
    const int wid   = tid >> 5;
    const int lane  = tid & 31;
    const int b     = blockIdx.x / NCHUNKS;
    const int chunk = blockIdx.x % NCHUNKS;
    const int n0    = chunk * CHUNK;

    // --- stage tiny t first so exp work can overlap the z-load chain ---
    if (tid == 0) nonuniform = 0;
    if (tid < CHUNK) t_s[tid] = t[b * NN + n0 + tid];       // XD == 1

    // issue independent loads early
    const int   m  = tid;                                   // one m-point per thread
    const float xm = x[b * MM + m];
    const float b0 = bias[0], b1 = bias[1];

    float4 zv, w0v, w1v;
    if (wid < CHUNK) {   // warps 0..7 own z row n0+wid
        zv  = ((const float4*)(z + (size_t)(b * NN + n0 + wid) * ZDIM))[lane];
        w0v = ((const float4*)W)[lane];
        w1v = ((const float4*)W)[32 + lane];
    }

    __syncthreads();     // bar1: t_s + flag init visible

    // sigma uniformity check (result read after bar2)
    const float s0 = sigma[0];
    if (tid < ZDIM && sigma[tid] != s0) atomicOr(&nonuniform, 1);

    // --- speculative fast-path exp terms (overlaps z latency) ---
    const float coef = -0.5f * __expf(-2.0f * s0);
    float e[CHUNK];
#pragma unroll
    for (int n = 0; n < CHUNK; ++n) {
        const float d = xm - t_s[n];
        e[n] = __expf(coef * d * d);
    }

    // --- zw chunk: warp w reduces row n0+w ---
    if (wid < CHUNK) {
        float a0 = zv.x * w0v.x;  a0 = fmaf(zv.y, w0v.y, a0);
        a0 = fmaf(zv.z, w0v.z, a0); a0 = fmaf(zv.w, w0v.w, a0);
        float a1 = zv.x * w1v.x;  a1 = fmaf(zv.y, w1v.y, a1);
        a1 = fmaf(zv.z, w1v.z, a1); a1 = fmaf(zv.w, w1v.w, a1);
#pragma unroll
        for (int o = 16; o; o >>= 1) {
            a0 += __shfl_xor_sync(0xFFFFFFFFu, a0, o);
            a1 += __shfl_xor_sync(0xFFFFFFFFu, a1, o);
        }
        if (lane == 0) { zw0_s[wid] = a0; zw1_s[wid] = a1; }
    }
    __syncthreads();     // bar2: zw ready, nonuniform final

    float s_0, s_1;
    if (!nonuniform) {
        s_0 = e[0] * zw0_s[0];
        s_1 = e[0] * zw1_s[0];
#pragma unroll
        for (int n = 1; n < CHUNK; ++n) {
            s_0 = fmaf(e[n], zw0_s[n], s_0);
            s_1 = fmaf(e[n], zw1_s[n], s_1);
        }
    } else {
        // general path: per-channel length scales (correct for any sigma)
        s_0 = 0.f; s_1 = 0.f;
        for (int n = 0; n < CHUNK; ++n) {
            const float d  = xm - t_s[n];
            const float d2 = d * d;
            const float* zr = z + (size_t)(b * NN + n0 + n) * ZDIM;
            for (int c = 0; c < ZDIM; ++c) {
                const float inv = __expf(-sigma[c]);
                const float q   = -0.5f * inv * inv;
                const float ev  = zr[c] * __expf(q * d2);
                s_0 = fmaf(ev, W[c],        s_0);
                s_1 = fmaf(ev, W[ZDIM + c], s_1);
            }
        }
    }

    // --- relaxed accumulate + acq_rel counter; last arriver finalizes ---
    const int   pt   = b * MM + m;           // 0..2047
    float*      acc  = g_acc + 2 * pt;
    red_add_f32(acc + 0, s_0);
    red_add_f32(acc + 1, s_1);
    const unsigned old = atom_inc_acqrel(&g_cnt[pt]);
    if (old == NCONTRIB - 1) {
        const float a0 = ld_relaxed_f32(acc + 0);
        const float a1 = ld_relaxed_f32(acc + 1);
        out[2 * pt + 0] = a0 + b0;
        out[2 * pt + 1] = a1 + b1;
        st_relaxed_f32(acc + 0, 0.0f);       // reset for next graph replay
        st_relaxed_f32(acc + 1, 0.0f);
        st_relaxed_u32(&g_cnt[pt], 0u);
    }
}

// ---------------------------------------------------------------------------
extern "C" void kernel_launch(void* const* d_in, const int* in_sizes, int n_in,
                              void* d_out, int out_size) {
    const float* t     = (const float*)d_in[0];
    const float* z     = (const float*)d_in[1];
    const float* x     = (const float*)d_in[2];
    const float* sigma = (const float*)d_in[3];
    const float* W     = (const float*)d_in[4];
    const float* bias  = (const float*)d_in[5];
    float* out = (float*)d_out;

    decoder_v5<<<GRID, NTHREADS>>>(t, z, x, sigma, W, bias, out);
}